// round 2
// baseline (speedup 1.0000x reference)
#include <cuda_runtime.h>
#include <cuda_fp16.h>
#include <cstdint>

#define CZ      128
#define TILE_M  128
#define NROWS   (512*512)
#define NTILES  (NROWS/TILE_M)   /* 2048 */
#define THREADS 256

#define ZSTRH   136              /* halves per padded row  */
#define ZSTRB   272              /* bytes per padded row   */
#define WMAT_H  (128*ZSTRH)      /* halves per weight tile */
#define WMAT_B  (128*ZSTRB)      /* 34816 bytes            */

/* smem layout (bytes) */
#define SM_MASK 0                   /* 128 f32 */
#define SM_BIAS 512                 /* 640 f32: apb|agb|bpb|bgb|gb */
#define SM_Z    3072                /* z tile, half [128][136] */
#define SM_W0   (SM_Z  + WMAT_B)    /* 37888 */
#define SM_W1   (SM_W0 + WMAT_B)    /* 72704 */
#define SMEM_TOTAL (SM_W1 + WMAT_B) /* 107520 */

/* fp16 weight scratch, pre-converted+padded by prep kernel */
__device__ __align__(16) __half g_wh[5 * WMAT_H];

__global__ void cvt_weights(const float* __restrict__ w0, const float* __restrict__ w1,
                            const float* __restrict__ w2, const float* __restrict__ w3,
                            const float* __restrict__ w4) {
    int i = blockIdx.x * blockDim.x + threadIdx.x;   /* 0 .. 81919 */
    int m = i >> 14, idx = i & 16383;
    const float* w = (m == 0) ? w0 : (m == 1) ? w1 : (m == 2) ? w2 : (m == 3) ? w3 : w4;
    int r = idx >> 7, c = idx & 127;
    g_wh[m * WMAT_H + r * ZSTRH + c] = __float2half_rn(w[idx]);
}

__device__ __forceinline__ uint32_t smem_u32(const void* p) {
    uint32_t a;
    asm("{ .reg .u64 t; cvta.to.shared.u64 t, %1; cvt.u32.u64 %0, t; }" : "=r"(a) : "l"(p));
    return a;
}

__device__ __forceinline__ void cp16(uint32_t s, uint64_t g) {
    asm volatile("cp.async.cg.shared.global [%0], [%1], 16;" :: "r"(s), "l"(g) : "memory");
}
#define CP_COMMIT() asm volatile("cp.async.commit_group;" ::: "memory")
#define CP_WAIT(n)  asm volatile("cp.async.wait_group %0;" :: "n"(n) : "memory")

__device__ __forceinline__ void copy_w(uint32_t sdst, int m, int tid) {
    const char* src = (const char*)g_wh + (size_t)m * WMAT_B;
#pragma unroll
    for (int i = tid; i < WMAT_B / 16; i += THREADS)
        cp16(sdst + i * 16, (uint64_t)__cvta_generic_to_global(src + i * 16));
}

__device__ __forceinline__ void ldm_x4(uint32_t (&d)[4], uint32_t a) {
    asm volatile("ldmatrix.sync.aligned.m8n8.x4.shared.b16 {%0,%1,%2,%3}, [%4];"
                 : "=r"(d[0]), "=r"(d[1]), "=r"(d[2]), "=r"(d[3]) : "r"(a));
}
__device__ __forceinline__ void ldm_x2(uint32_t (&d)[2], uint32_t a) {
    asm volatile("ldmatrix.sync.aligned.m8n8.x2.shared.b16 {%0,%1}, [%2];"
                 : "=r"(d[0]), "=r"(d[1]) : "r"(a));
}
__device__ __forceinline__ void mma16816(float (&c)[4], const uint32_t (&a)[4],
                                         const uint32_t (&b)[2]) {
    asm volatile("mma.sync.aligned.m16n8k16.row.col.f32.f16.f16.f32 "
                 "{%0,%1,%2,%3}, {%4,%5,%6,%7}, {%8,%9}, {%0,%1,%2,%3};"
                 : "+f"(c[0]), "+f"(c[1]), "+f"(c[2]), "+f"(c[3])
                 : "r"(a[0]), "r"(a[1]), "r"(a[2]), "r"(a[3]), "r"(b[0]), "r"(b[1]));
}

/* one 128x128x128 gemm: warp (m0,n0) computes m32 x n64 */
__device__ __forceinline__ void gemm128(uint32_t zb, uint32_t wb,
                                        float (&acc)[2][8][4], int lane, int m0, int n0) {
#pragma unroll
    for (int mt = 0; mt < 2; mt++)
#pragma unroll
        for (int nt = 0; nt < 8; nt++)
#pragma unroll
            for (int r = 0; r < 4; r++) acc[mt][nt][r] = 0.f;

    const int arow = lane & 15, asel = (lane >> 4) << 3;       /* A: rows, k-half */
    const int brow = lane & 7,  bsel = ((lane >> 3) & 1) << 3; /* B: n-rows, k-half */
#pragma unroll
    for (int kt = 0; kt < 8; kt++) {
        int k = kt * 16;
        uint32_t a[2][4];
#pragma unroll
        for (int mt = 0; mt < 2; mt++)
            ldm_x4(a[mt], zb + (uint32_t)((m0 + mt * 16 + arow) * ZSTRB + (k + asel) * 2));
        uint32_t b[8][2];
#pragma unroll
        for (int nt = 0; nt < 8; nt++)
            ldm_x2(b[nt], wb + (uint32_t)((n0 + nt * 8 + brow) * ZSTRB + (k + bsel) * 2));
#pragma unroll
        for (int mt = 0; mt < 2; mt++)
#pragma unroll
            for (int nt = 0; nt < 8; nt++)
                mma16816(acc[mt][nt], a[mt], b[nt]);
    }
}

__device__ __forceinline__ float sigmf(float v) { return 1.0f / (1.0f + __expf(-v)); }

__device__ __forceinline__ void epi_pair(const float (&p)[2][8][4], const float (&g)[2][8][4],
                                         float* __restrict__ ob, long row0,
                                         const float* __restrict__ smask,
                                         const float* __restrict__ pb,
                                         const float* __restrict__ gbv,
                                         int m0, int n0, int lane) {
    int tig = lane & 3, grp = lane >> 2;
#pragma unroll
    for (int mt = 0; mt < 2; mt++) {
        int ra = m0 + mt * 16 + grp, rb = ra + 8;
        float ma = smask[ra], mb = smask[rb];
        float* pa = ob + (row0 + ra) * CZ;
        float* pz = ob + (row0 + rb) * CZ;
#pragma unroll
        for (int nt = 0; nt < 8; nt++) {
            int c = n0 + nt * 8 + tig * 2;
            float b0 = pb[c], b1 = pb[c + 1], g0 = gbv[c], g1 = gbv[c + 1];
            float2 v0, v1;
            v0.x = ma * sigmf(g[mt][nt][0] + g0) * (p[mt][nt][0] + b0);
            v0.y = ma * sigmf(g[mt][nt][1] + g1) * (p[mt][nt][1] + b1);
            v1.x = mb * sigmf(g[mt][nt][2] + g0) * (p[mt][nt][2] + b0);
            v1.y = mb * sigmf(g[mt][nt][3] + g1) * (p[mt][nt][3] + b1);
            *(float2*)(pa + c) = v0;
            *(float2*)(pz + c) = v1;
        }
    }
}

__device__ __forceinline__ void epi_g(const float (&d)[2][8][4], float* __restrict__ ob,
                                      long row0, const float* __restrict__ gbv,
                                      int m0, int n0, int lane) {
    int tig = lane & 3, grp = lane >> 2;
#pragma unroll
    for (int mt = 0; mt < 2; mt++) {
        int ra = m0 + mt * 16 + grp, rb = ra + 8;
        float* pa = ob + (row0 + ra) * CZ;
        float* pz = ob + (row0 + rb) * CZ;
#pragma unroll
        for (int nt = 0; nt < 8; nt++) {
            int c = n0 + nt * 8 + tig * 2;
            float g0 = gbv[c], g1 = gbv[c + 1];
            float2 v0, v1;
            v0.x = sigmf(d[mt][nt][0] + g0);
            v0.y = sigmf(d[mt][nt][1] + g1);
            v1.x = sigmf(d[mt][nt][2] + g0);
            v1.y = sigmf(d[mt][nt][3] + g1);
            *(float2*)(pa + c) = v0;
            *(float2*)(pz + c) = v1;
        }
    }
}

__global__ void __launch_bounds__(THREADS, 1)
tri_kernel(const float* __restrict__ x,   const float* __restrict__ mask,
           const float* __restrict__ lnw, const float* __restrict__ lnb,
           const float* __restrict__ apb, const float* __restrict__ agb,
           const float* __restrict__ bpb, const float* __restrict__ bgb,
           const float* __restrict__ gb,  float* __restrict__ out) {
    extern __shared__ char smem[];
    const uint32_t sbase = smem_u32(smem);
    const int tid = threadIdx.x, wid = tid >> 5, lane = tid & 31;
    const long row0 = (long)blockIdx.x * TILE_M;
    const int m0 = (wid >> 1) * 32, n0 = (wid & 1) * 64;

    /* biases + mask */
    float* sb    = (float*)(smem + SM_BIAS);
    float* smask = (float*)(smem + SM_MASK);
    for (int i = tid; i < 640; i += THREADS) {
        int j = i & 127, which = i >> 7;
        sb[i] = (which == 0) ? apb[j] : (which == 1) ? agb[j] :
                (which == 2) ? bpb[j] : (which == 3) ? bgb[j] : gb[j];
    }
    if (tid < TILE_M) smask[tid] = mask[row0 + tid];

    /* LayerNorm -> fp16 z tile. warp w: rows w*16..+15, lane: 4 channels */
    {
        float4 w4 = *(const float4*)(lnw + lane * 4);
        float4 b4 = *(const float4*)(lnb + lane * 4);
        char* zrow = smem + SM_Z;
#pragma unroll 4
        for (int i = 0; i < 16; i++) {
            int r = wid * 16 + i;
            float4 v = *(const float4*)(x + (row0 + r) * CZ + lane * 4);
            float s  = v.x + v.y + v.z + v.w;
            float ss = v.x * v.x + v.y * v.y + v.z * v.z + v.w * v.w;
#pragma unroll
            for (int o = 16; o; o >>= 1) {
                s  += __shfl_xor_sync(0xFFFFFFFFu, s, o);
                ss += __shfl_xor_sync(0xFFFFFFFFu, ss, o);
            }
            float mu  = s * (1.0f / 128.0f);
            float var = ss * (1.0f / 128.0f) - mu * mu;
            float rs  = rsqrtf(var + 1e-5f);
            __half2 h01 = __floats2half2_rn((v.x - mu) * rs * w4.x + b4.x,
                                            (v.y - mu) * rs * w4.y + b4.y);
            __half2 h23 = __floats2half2_rn((v.z - mu) * rs * w4.z + b4.z,
                                            (v.w - mu) * rs * w4.w + b4.w);
            uint2 u;
            u.x = *(uint32_t*)&h01;
            u.y = *(uint32_t*)&h23;
            *(uint2*)(zrow + r * ZSTRB + lane * 8) = u;
        }
    }

    /* prefetch a_p, a_g */
    copy_w(sbase + SM_W0, 0, tid); CP_COMMIT();
    copy_w(sbase + SM_W1, 1, tid); CP_COMMIT();

    float accP[2][8][4], accG[2][8][4];
    const uint32_t zb = sbase + SM_Z, w0b = sbase + SM_W0, w1b = sbase + SM_W1;

    /* stage 0: a_p */
    CP_WAIT(1); __syncthreads();
    gemm128(zb, w0b, accP, lane, m0, n0);
    __syncthreads();
    copy_w(w0b, 2, tid); CP_COMMIT();               /* b_p -> buf0 */

    /* stage 1: a_g */
    CP_WAIT(1); __syncthreads();
    gemm128(zb, w1b, accG, lane, m0, n0);
    __syncthreads();
    copy_w(w1b, 3, tid); CP_COMMIT();               /* b_g -> buf1 */
    epi_pair(accP, accG, out, row0, smask, sb, sb + 128, m0, n0, lane);

    /* stage 2: b_p */
    CP_WAIT(1); __syncthreads();
    gemm128(zb, w0b, accP, lane, m0, n0);
    __syncthreads();
    copy_w(w0b, 4, tid); CP_COMMIT();               /* g -> buf0 */

    /* stage 3: b_g */
    CP_WAIT(1); __syncthreads();
    gemm128(zb, w1b, accG, lane, m0, n0);
    epi_pair(accP, accG, out + (long)NROWS * CZ, row0, smask,
             sb + 256, sb + 384, m0, n0, lane);

    /* stage 4: g */
    CP_WAIT(0); __syncthreads();
    gemm128(zb, w0b, accP, lane, m0, n0);
    epi_g(accP, out + 2L * NROWS * CZ, row0, sb + 512, m0, n0, lane);
}

extern "C" void kernel_launch(void* const* d_in, const int* in_sizes, int n_in,
                              void* d_out, int out_size) {
    const float* x    = (const float*)d_in[0];
    const float* mask = (const float*)d_in[1];
    const float* lnw  = (const float*)d_in[2];
    const float* lnb  = (const float*)d_in[3];
    const float* apw  = (const float*)d_in[4];
    const float* apb  = (const float*)d_in[5];
    const float* agw  = (const float*)d_in[6];
    const float* agb  = (const float*)d_in[7];
    const float* bpw  = (const float*)d_in[8];
    const float* bpb  = (const float*)d_in[9];
    const float* bgw  = (const float*)d_in[10];
    const float* bgb  = (const float*)d_in[11];
    const float* gw   = (const float*)d_in[12];
    const float* gb   = (const float*)d_in[13];
    float* out = (float*)d_out;

    cvt_weights<<<320, 256>>>(apw, agw, bpw, bgw, gw);

    cudaFuncSetAttribute(tri_kernel, cudaFuncAttributeMaxDynamicSharedMemorySize, SMEM_TOTAL);
    tri_kernel<<<NTILES, THREADS, SMEM_TOTAL>>>(x, mask, lnw, lnb,
                                                apb, agb, bpb, bgb, gb, out);
}

// round 4
// speedup vs baseline: 1.2628x; 1.2628x over previous
#include <cuda_runtime.h>
#include <cuda_fp16.h>
#include <cstdint>

#define CZ      128
#define TILE_M  128
#define NROWS   (512*512)
#define NTILES  (NROWS/TILE_M)   /* 2048 */
#define THREADS 512

#define ZSTRH   136              /* halves per padded row  */
#define ZSTRB   272              /* bytes per padded row   */
#define WMAT_H  (128*ZSTRH)      /* halves per weight tile */
#define WMAT_B  (128*ZSTRB)      /* 34816 bytes            */

/* smem layout (bytes) */
#define SM_MASK 0                   /* 128 f32 */
#define SM_BIAS 512                 /* 640 f32: apb|agb|bpb|bgb|gb */
#define SM_Z    3072                /* z tile, half [128][136] */
#define SM_W(i) (SM_Z + WMAT_B + (i) * WMAT_B)
#define SMEM_TOTAL (SM_Z + 6 * WMAT_B)   /* 211968 */

/* fp16 weight scratch, pre-converted+padded by prep kernel */
__device__ __align__(16) __half g_wh[5 * WMAT_H];

__global__ void cvt_weights(const float* __restrict__ w0, const float* __restrict__ w1,
                            const float* __restrict__ w2, const float* __restrict__ w3,
                            const float* __restrict__ w4) {
    int i = blockIdx.x * blockDim.x + threadIdx.x;   /* 0 .. 81919 */
    int m = i >> 14, idx = i & 16383;
    const float* w = (m == 0) ? w0 : (m == 1) ? w1 : (m == 2) ? w2 : (m == 3) ? w3 : w4;
    int r = idx >> 7, c = idx & 127;
    g_wh[m * WMAT_H + r * ZSTRH + c] = __float2half_rn(w[idx]);
}

__device__ __forceinline__ uint32_t smem_u32(const void* p) {
    uint32_t a;
    asm("{ .reg .u64 t; cvta.to.shared.u64 t, %1; cvt.u32.u64 %0, t; }" : "=r"(a) : "l"(p));
    return a;
}

__device__ __forceinline__ void cp16(uint32_t s, uint64_t g) {
    asm volatile("cp.async.cg.shared.global [%0], [%1], 16;" :: "r"(s), "l"(g) : "memory");
}
#define CP_COMMIT() asm volatile("cp.async.commit_group;" ::: "memory")
#define CP_WAIT(n)  asm volatile("cp.async.wait_group %0;" :: "n"(n) : "memory")

__device__ __forceinline__ void copy_w(uint32_t sdst, int m, int tid) {
    const char* src = (const char*)g_wh + (size_t)m * WMAT_B;
#pragma unroll
    for (int i = tid; i < WMAT_B / 16; i += THREADS)
        cp16(sdst + i * 16, (uint64_t)__cvta_generic_to_global(src + i * 16));
}

__device__ __forceinline__ void ldm_x4(uint32_t (&d)[4], uint32_t a) {
    asm volatile("ldmatrix.sync.aligned.m8n8.x4.shared.b16 {%0,%1,%2,%3}, [%4];"
                 : "=r"(d[0]), "=r"(d[1]), "=r"(d[2]), "=r"(d[3]) : "r"(a));
}
__device__ __forceinline__ void mma16816(float (&c)[4], const uint32_t (&a)[4],
                                         uint32_t b0, uint32_t b1) {
    asm volatile("mma.sync.aligned.m16n8k16.row.col.f32.f16.f16.f32 "
                 "{%0,%1,%2,%3}, {%4,%5,%6,%7}, {%8,%9}, {%0,%1,%2,%3};"
                 : "+f"(c[0]), "+f"(c[1]), "+f"(c[2]), "+f"(c[3])
                 : "r"(a[0]), "r"(a[1]), "r"(a[2]), "r"(a[3]), "r"(b0), "r"(b1));
}

/* fused gemm over one m16 x n64 warp tile; PAIR: two weight matrices share A */
template <bool PAIR>
__device__ __forceinline__ void gemm_tile(uint32_t zb, uint32_t wp, uint32_t wg,
                                          float (&accP)[8][4], float (&accG)[8][4],
                                          int lane, int m0, int n0) {
#pragma unroll
    for (int nt = 0; nt < 8; nt++)
#pragma unroll
        for (int r = 0; r < 4; r++) { accP[nt][r] = 0.f; if (PAIR) accG[nt][r] = 0.f; }

    /* ldmatrix x4 address pattern (both A and B): lane -> row (lane&15), k-half (lane>>4) */
    const uint32_t rsel = (uint32_t)(lane & 15) * ZSTRB + (uint32_t)((lane >> 4) << 4);
    const uint32_t abase = zb + (uint32_t)m0 * ZSTRB + rsel;
#pragma unroll
    for (int kt = 0; kt < 8; kt++) {
        const uint32_t koff = (uint32_t)kt * 32;   /* 16 halves */
        uint32_t a[4];
        ldm_x4(a, abase + koff);
#pragma unroll
        for (int pr = 0; pr < 4; pr++) {
            const uint32_t nsel = (uint32_t)(n0 + pr * 16) * ZSTRB + rsel + koff;
            uint32_t bp[4];
            ldm_x4(bp, wp + nsel);
            mma16816(accP[2 * pr + 0], a, bp[0], bp[2]);
            mma16816(accP[2 * pr + 1], a, bp[1], bp[3]);
            if (PAIR) {
                uint32_t bg[4];
                ldm_x4(bg, wg + nsel);
                mma16816(accG[2 * pr + 0], a, bg[0], bg[2]);
                mma16816(accG[2 * pr + 1], a, bg[1], bg[3]);
            }
        }
    }
}

__device__ __forceinline__ float sigmf(float v) { return 1.0f / (1.0f + __expf(-v)); }

/* epilogue, m16 x n64 warp tile: out = mask * sigmoid(G + gb) * (P + pb) */
__device__ __forceinline__ void epi_pair(const float (&p)[8][4], const float (&g)[8][4],
                                         float* __restrict__ ob, long row0,
                                         const float* __restrict__ smask,
                                         const float* __restrict__ pb,
                                         const float* __restrict__ gbv,
                                         int m0, int n0, int lane) {
    int tig = lane & 3, grp = lane >> 2;
    int ra = m0 + grp, rb = ra + 8;
    float ma = smask[ra], mb = smask[rb];
    float* pa = ob + (row0 + ra) * CZ;
    float* pz = ob + (row0 + rb) * CZ;
#pragma unroll
    for (int nt = 0; nt < 8; nt++) {
        int c = n0 + nt * 8 + tig * 2;
        float b0 = pb[c], b1 = pb[c + 1], g0 = gbv[c], g1 = gbv[c + 1];
        float2 v0, v1;
        v0.x = ma * sigmf(g[nt][0] + g0) * (p[nt][0] + b0);
        v0.y = ma * sigmf(g[nt][1] + g1) * (p[nt][1] + b1);
        v1.x = mb * sigmf(g[nt][2] + g0) * (p[nt][2] + b0);
        v1.y = mb * sigmf(g[nt][3] + g1) * (p[nt][3] + b1);
        *(float2*)(pa + c) = v0;
        *(float2*)(pz + c) = v1;
    }
}

__device__ __forceinline__ void epi_g(const float (&d)[8][4], float* __restrict__ ob,
                                      long row0, const float* __restrict__ gbv,
                                      int m0, int n0, int lane) {
    int tig = lane & 3, grp = lane >> 2;
    int ra = m0 + grp, rb = ra + 8;
    float* pa = ob + (row0 + ra) * CZ;
    float* pz = ob + (row0 + rb) * CZ;
#pragma unroll
    for (int nt = 0; nt < 8; nt++) {
        int c = n0 + nt * 8 + tig * 2;
        float g0 = gbv[c], g1 = gbv[c + 1];
        float2 v0, v1;
        v0.x = sigmf(d[nt][0] + g0);
        v0.y = sigmf(d[nt][1] + g1);
        v1.x = sigmf(d[nt][2] + g0);
        v1.y = sigmf(d[nt][3] + g1);
        *(float2*)(pa + c) = v0;
        *(float2*)(pz + c) = v1;
    }
}

__global__ void __launch_bounds__(THREADS, 1)
tri_kernel(const float* __restrict__ x,   const float* __restrict__ mask,
           const float* __restrict__ lnw, const float* __restrict__ lnb,
           const float* __restrict__ apb, const float* __restrict__ agb,
           const float* __restrict__ bpb, const float* __restrict__ bgb,
           const float* __restrict__ gb,  float* __restrict__ out) {
    extern __shared__ char smem[];
    const uint32_t sbase = smem_u32(smem);
    const int tid = threadIdx.x, wid = tid >> 5, lane = tid & 31;
    const long row0 = (long)blockIdx.x * TILE_M;
    /* 16 warps: 8 m-groups x 2 n-groups; warp tile m16 x n64 */
    const int m0 = (wid >> 1) * 16, n0 = (wid & 1) * 64;

    /* all 5 weight matrices -> smem upfront, overlapped with LayerNorm below */
    copy_w(sbase + SM_W(0), 0, tid);
    copy_w(sbase + SM_W(1), 1, tid); CP_COMMIT();    /* group: ap+ag */
    copy_w(sbase + SM_W(2), 2, tid);
    copy_w(sbase + SM_W(3), 3, tid); CP_COMMIT();    /* group: bp+bg */
    copy_w(sbase + SM_W(4), 4, tid); CP_COMMIT();    /* group: g     */

    /* biases + mask */
    float* sb    = (float*)(smem + SM_BIAS);
    float* smask = (float*)(smem + SM_MASK);
    for (int i = tid; i < 640; i += THREADS) {
        int j = i & 127, which = i >> 7;
        sb[i] = (which == 0) ? apb[j] : (which == 1) ? agb[j] :
                (which == 2) ? bpb[j] : (which == 3) ? bgb[j] : gb[j];
    }
    if (tid < TILE_M) smask[tid] = mask[row0 + tid];

    /* LayerNorm -> fp16 z tile. warp w: rows w*8..+7, lane: 4 channels */
    {
        float4 w4 = *(const float4*)(lnw + lane * 4);
        float4 b4 = *(const float4*)(lnb + lane * 4);
        char* zrow = smem + SM_Z;
#pragma unroll 4
        for (int i = 0; i < 8; i++) {
            int r = wid * 8 + i;
            float4 v = *(const float4*)(x + (row0 + r) * CZ + lane * 4);
            float s  = v.x + v.y + v.z + v.w;
            float ss = v.x * v.x + v.y * v.y + v.z * v.z + v.w * v.w;
#pragma unroll
            for (int o = 16; o; o >>= 1) {
                s  += __shfl_xor_sync(0xFFFFFFFFu, s, o);
                ss += __shfl_xor_sync(0xFFFFFFFFu, ss, o);
            }
            float mu  = s * (1.0f / 128.0f);
            float var = ss * (1.0f / 128.0f) - mu * mu;
            float rs  = rsqrtf(var + 1e-5f);
            __half2 h01 = __floats2half2_rn((v.x - mu) * rs * w4.x + b4.x,
                                            (v.y - mu) * rs * w4.y + b4.y);
            __half2 h23 = __floats2half2_rn((v.z - mu) * rs * w4.z + b4.z,
                                            (v.w - mu) * rs * w4.w + b4.w);
            uint2 u;
            u.x = *(uint32_t*)&h01;
            u.y = *(uint32_t*)&h23;
            *(uint2*)(zrow + r * ZSTRB + lane * 8) = u;
        }
    }

    float accP[8][4], accG[8][4];
    const uint32_t zb = sbase + SM_Z;

    /* stage a: needs z + ap/ag */
    CP_WAIT(2); __syncthreads();
    gemm_tile<true>(zb, sbase + SM_W(0), sbase + SM_W(1), accP, accG, lane, m0, n0);
    epi_pair(accP, accG, out, row0, smask, sb, sb + 128, m0, n0, lane);

    /* stage b */
    CP_WAIT(1); __syncthreads();
    gemm_tile<true>(zb, sbase + SM_W(2), sbase + SM_W(3), accP, accG, lane, m0, n0);
    epi_pair(accP, accG, out + (long)NROWS * CZ, row0, smask,
             sb + 256, sb + 384, m0, n0, lane);

    /* stage g */
    CP_WAIT(0); __syncthreads();
    gemm_tile<false>(zb, sbase + SM_W(4), sbase + SM_W(4), accP, accG, lane, m0, n0);
    epi_g(accP, out + 2L * NROWS * CZ, row0, sb + 512, m0, n0, lane);
}

extern "C" void kernel_launch(void* const* d_in, const int* in_sizes, int n_in,
                              void* d_out, int out_size) {
    const float* x    = (const float*)d_in[0];
    const float* mask = (const float*)d_in[1];
    const float* lnw  = (const float*)d_in[2];
    const float* lnb  = (const float*)d_in[3];
    const float* apw  = (const float*)d_in[4];
    const float* apb  = (const float*)d_in[5];
    const float* agw  = (const float*)d_in[6];
    const float* agb  = (const float*)d_in[7];
    const float* bpw  = (const float*)d_in[8];
    const float* bpb  = (const float*)d_in[9];
    const float* bgw  = (const float*)d_in[10];
    const float* bgb  = (const float*)d_in[11];
    const float* gw   = (const float*)d_in[12];
    const float* gb   = (const float*)d_in[13];
    float* out = (float*)d_out;

    cvt_weights<<<320, 256>>>(apw, agw, bpw, bgw, gw);

    cudaFuncSetAttribute(tri_kernel, cudaFuncAttributeMaxDynamicSharedMemorySize, SMEM_TOTAL);
    tri_kernel<<<NTILES, THREADS, SMEM_TOTAL>>>(x, mask, lnw, lnb,
                                                apb, agb, bpb, bgb, gb, out);
}

// round 5
// speedup vs baseline: 1.4402x; 1.1405x over previous
#include <cuda_runtime.h>
#include <cuda_fp16.h>
#include <cstdint>

#define CZ      128
#define NROWS   (512*512)
#define NTILES  2048
#define THREADS 512
#define GRID    152

#define ZROWB   256                 /* bytes per 128-half row */
#define TILE_B  (128*ZROWB)         /* 32768 */

/* smem layout (bytes) */
#define SM_BIAS 0                   /* 640 f32: apb|agb|bpb|bgb|gb (2560 B) */
#define SM_Z0   2560
#define SM_Z1   (SM_Z0 + TILE_B)
#define SM_W(i) (SM_Z1 + TILE_B + (i) * TILE_B)
#define SMEM_TOTAL (SM_W(5))        /* 231936 <= 232448 */

/* fp16 weight scratch, pre-converted + pre-SWIZZLED by prep kernel */
__device__ __align__(16) __half g_wh[5 * 128 * 128];

/* swizzle: 16B chunk index ^= (row & 7). row stride 256B. */
__global__ void cvt_weights(const float* __restrict__ w0, const float* __restrict__ w1,
                            const float* __restrict__ w2, const float* __restrict__ w3,
                            const float* __restrict__ w4) {
    int i = blockIdx.x * blockDim.x + threadIdx.x;   /* 0 .. 81919 */
    int m = i >> 14, idx = i & 16383;
    const float* w = (m == 0) ? w0 : (m == 1) ? w1 : (m == 2) ? w2 : (m == 3) ? w3 : w4;
    int r = idx >> 7, c = idx & 127;
    int pos = r * 128 + ((((c >> 3) ^ (r & 7)) << 3) | (c & 7));
    g_wh[m * 16384 + pos] = __float2half_rn(w[idx]);
}

__device__ __forceinline__ uint32_t smem_u32(const void* p) {
    uint32_t a;
    asm("{ .reg .u64 t; cvta.to.shared.u64 t, %1; cvt.u32.u64 %0, t; }" : "=r"(a) : "l"(p));
    return a;
}

__device__ __forceinline__ void cp16(uint32_t s, uint64_t g) {
    asm volatile("cp.async.cg.shared.global [%0], [%1], 16;" :: "r"(s), "l"(g) : "memory");
}
#define CP_COMMIT() asm volatile("cp.async.commit_group;" ::: "memory")
#define CP_WAIT0()  asm volatile("cp.async.wait_group 0;" ::: "memory")

__device__ __forceinline__ void ldm_x4(uint32_t (&d)[4], uint32_t a) {
    asm volatile("ldmatrix.sync.aligned.m8n8.x4.shared.b16 {%0,%1,%2,%3}, [%4];"
                 : "=r"(d[0]), "=r"(d[1]), "=r"(d[2]), "=r"(d[3]) : "r"(a));
}
__device__ __forceinline__ void mma16816(float (&c)[4], const uint32_t (&a)[4],
                                         uint32_t b0, uint32_t b1) {
    asm volatile("mma.sync.aligned.m16n8k16.row.col.f32.f16.f16.f32 "
                 "{%0,%1,%2,%3}, {%4,%5,%6,%7}, {%8,%9}, {%0,%1,%2,%3};"
                 : "+f"(c[0]), "+f"(c[1]), "+f"(c[2]), "+f"(c[3])
                 : "r"(a[0]), "r"(a[1]), "r"(a[2]), "r"(a[3]), "r"(b0), "r"(b1));
}

/* fused gemm, warp tile m32 x n32; PAIR: two weight matrices share the A fragments */
template <bool PAIR>
__device__ __forceinline__ void gemm_tile(uint32_t zb, uint32_t wp, uint32_t wg,
                                          float (&accP)[2][4][4], float (&accG)[2][4][4],
                                          int lane, int m0, int n0) {
#pragma unroll
    for (int mt = 0; mt < 2; mt++)
#pragma unroll
        for (int nt = 0; nt < 4; nt++)
#pragma unroll
            for (int r = 0; r < 4; r++) { accP[mt][nt][r] = 0.f; if (PAIR) accG[mt][nt][r] = 0.f; }

    const uint32_t r  = (uint32_t)(lane & 15);
    const uint32_t s  = (uint32_t)(lane >> 4);
    const uint32_t x7 = (uint32_t)(lane & 7);
    uint32_t za0 = zb + (uint32_t)(m0 + r) * ZROWB;
    uint32_t za1 = za0 + 16 * ZROWB;
    uint32_t wp0 = wp + (uint32_t)(n0 + r) * ZROWB;
    uint32_t wp1 = wp0 + 16 * ZROWB;
    uint32_t wg0 = wg + (uint32_t)(n0 + r) * ZROWB;
    uint32_t wg1 = wg0 + 16 * ZROWB;

#pragma unroll
    for (int kt = 0; kt < 8; kt++) {
        const uint32_t off = (((uint32_t)(2 * kt) + s) ^ x7) << 4;
        uint32_t a0[4], a1[4], b0[4], b1[4];
        ldm_x4(a0, za0 + off);
        ldm_x4(a1, za1 + off);
        ldm_x4(b0, wp0 + off);
        ldm_x4(b1, wp1 + off);
        mma16816(accP[0][0], a0, b0[0], b0[2]); mma16816(accP[0][1], a0, b0[1], b0[3]);
        mma16816(accP[0][2], a0, b1[0], b1[2]); mma16816(accP[0][3], a0, b1[1], b1[3]);
        mma16816(accP[1][0], a1, b0[0], b0[2]); mma16816(accP[1][1], a1, b0[1], b0[3]);
        mma16816(accP[1][2], a1, b1[0], b1[2]); mma16816(accP[1][3], a1, b1[1], b1[3]);
        if (PAIR) {
            ldm_x4(b0, wg0 + off);
            ldm_x4(b1, wg1 + off);
            mma16816(accG[0][0], a0, b0[0], b0[2]); mma16816(accG[0][1], a0, b0[1], b0[3]);
            mma16816(accG[0][2], a0, b1[0], b1[2]); mma16816(accG[0][3], a0, b1[1], b1[3]);
            mma16816(accG[1][0], a1, b0[0], b0[2]); mma16816(accG[1][1], a1, b0[1], b0[3]);
            mma16816(accG[1][2], a1, b1[0], b1[2]); mma16816(accG[1][3], a1, b1[1], b1[3]);
        }
    }
}

__device__ __forceinline__ float sigmf(float v) { return 1.0f / (1.0f + __expf(-v)); }

__device__ __forceinline__ void epi_pair(const float (&p)[2][4][4], const float (&g)[2][4][4],
                                         float* __restrict__ ob, long row0,
                                         const float* __restrict__ maskg,
                                         const float* __restrict__ pb,
                                         const float* __restrict__ gbv,
                                         int m0, int n0, int lane) {
    int tig = lane & 3, grp = lane >> 2;
#pragma unroll
    for (int mt = 0; mt < 2; mt++) {
        int ra = m0 + mt * 16 + grp, rb = ra + 8;
        float ma = __ldg(maskg + row0 + ra), mb = __ldg(maskg + row0 + rb);
        float* pa = ob + (row0 + ra) * CZ;
        float* pz = ob + (row0 + rb) * CZ;
#pragma unroll
        for (int nt = 0; nt < 4; nt++) {
            int c = n0 + nt * 8 + tig * 2;
            float b0 = pb[c], b1 = pb[c + 1], g0 = gbv[c], g1 = gbv[c + 1];
            float2 v0, v1;
            v0.x = ma * sigmf(g[mt][nt][0] + g0) * (p[mt][nt][0] + b0);
            v0.y = ma * sigmf(g[mt][nt][1] + g1) * (p[mt][nt][1] + b1);
            v1.x = mb * sigmf(g[mt][nt][2] + g0) * (p[mt][nt][2] + b0);
            v1.y = mb * sigmf(g[mt][nt][3] + g1) * (p[mt][nt][3] + b1);
            *(float2*)(pa + c) = v0;
            *(float2*)(pz + c) = v1;
        }
    }
}

__device__ __forceinline__ void epi_g(const float (&d)[2][4][4], float* __restrict__ ob,
                                      long row0, const float* __restrict__ gbv,
                                      int m0, int n0, int lane) {
    int tig = lane & 3, grp = lane >> 2;
#pragma unroll
    for (int mt = 0; mt < 2; mt++) {
        int ra = m0 + mt * 16 + grp, rb = ra + 8;
        float* pa = ob + (row0 + ra) * CZ;
        float* pz = ob + (row0 + rb) * CZ;
#pragma unroll
        for (int nt = 0; nt < 4; nt++) {
            int c = n0 + nt * 8 + tig * 2;
            float g0 = gbv[c], g1 = gbv[c + 1];
            float2 v0, v1;
            v0.x = sigmf(d[mt][nt][0] + g0);
            v0.y = sigmf(d[mt][nt][1] + g1);
            v1.x = sigmf(d[mt][nt][2] + g0);
            v1.y = sigmf(d[mt][nt][3] + g1);
            *(float2*)(pa + c) = v0;
            *(float2*)(pz + c) = v1;
        }
    }
}

/* LayerNorm one 128-row tile into swizzled fp16 z buffer. warp w: rows w*8..+7 */
__device__ __forceinline__ void do_ln(const float* __restrict__ x, long row0, char* zb,
                                      const float4& w4, const float4& b4,
                                      int wid, int lane) {
    const uint32_t chunk = (uint32_t)(lane >> 1);
    const uint32_t sub   = (uint32_t)(lane & 1) << 3;
#pragma unroll 4
    for (int i = 0; i < 8; i++) {
        int r = wid * 8 + i;
        float4 v = *(const float4*)(x + (row0 + r) * CZ + lane * 4);
        float s  = v.x + v.y + v.z + v.w;
        float ss = v.x * v.x + v.y * v.y + v.z * v.z + v.w * v.w;
#pragma unroll
        for (int o = 16; o; o >>= 1) {
            s  += __shfl_xor_sync(0xFFFFFFFFu, s, o);
            ss += __shfl_xor_sync(0xFFFFFFFFu, ss, o);
        }
        float mu  = s * (1.0f / 128.0f);
        float var = ss * (1.0f / 128.0f) - mu * mu;
        float rs  = rsqrtf(var + 1e-5f);
        __half2 h01 = __floats2half2_rn((v.x - mu) * rs * w4.x + b4.x,
                                        (v.y - mu) * rs * w4.y + b4.y);
        __half2 h23 = __floats2half2_rn((v.z - mu) * rs * w4.z + b4.z,
                                        (v.w - mu) * rs * w4.w + b4.w);
        uint2 u;
        u.x = *(uint32_t*)&h01;
        u.y = *(uint32_t*)&h23;
        uint32_t sw = ((chunk ^ (uint32_t)(r & 7)) << 4) | sub;
        *(uint2*)(zb + (uint32_t)r * ZROWB + sw) = u;
    }
}

__global__ void __launch_bounds__(THREADS, 1)
tri_kernel(const float* __restrict__ x,   const float* __restrict__ mask,
           const float* __restrict__ lnw, const float* __restrict__ lnb,
           const float* __restrict__ apb, const float* __restrict__ agb,
           const float* __restrict__ bpb, const float* __restrict__ bgb,
           const float* __restrict__ gb,  float* __restrict__ out) {
    extern __shared__ char smem[];
    const uint32_t sbase = smem_u32(smem);
    const int tid = threadIdx.x, wid = tid >> 5, lane = tid & 31;
    /* 16 warps: 4 m-groups x 4 n-groups; warp tile m32 x n32 */
    const int m0 = (wid >> 2) * 32, n0 = (wid & 3) * 32;

    /* one-time: all 5 weight matrices -> resident smem */
    {
        const char* src = (const char*)g_wh;
#pragma unroll
        for (int i = tid; i < 5 * TILE_B / 16; i += THREADS)
            cp16(sbase + SM_W(0) + i * 16, (uint64_t)__cvta_generic_to_global(src + i * 16));
        CP_COMMIT();
    }

    /* one-time: biases */
    float* sb = (float*)(smem + SM_BIAS);
    for (int i = tid; i < 640; i += THREADS) {
        int j = i & 127, which = i >> 7;
        sb[i] = (which == 0) ? apb[j] : (which == 1) ? agb[j] :
                (which == 2) ? bpb[j] : (which == 3) ? bgb[j] : gb[j];
    }

    const float4 lw4 = *(const float4*)(lnw + lane * 4);
    const float4 lb4 = *(const float4*)(lnb + lane * 4);

    int t = blockIdx.x;
    int buf = 0;
    do_ln(x, (long)t * 128, smem + SM_Z0, lw4, lb4, wid, lane);
    CP_WAIT0();
    __syncthreads();

    float accP[2][4][4], accG[2][4][4];
    for (;;) {
        const long row0 = (long)t * 128;
        const uint32_t zb = sbase + (buf ? SM_Z1 : SM_Z0);

        gemm_tile<true>(zb, sbase + SM_W(0), sbase + SM_W(1), accP, accG, lane, m0, n0);
        epi_pair(accP, accG, out, row0, mask, sb, sb + 128, m0, n0, lane);

        gemm_tile<true>(zb, sbase + SM_W(2), sbase + SM_W(3), accP, accG, lane, m0, n0);
        epi_pair(accP, accG, out + (long)NROWS * CZ, row0, mask,
                 sb + 256, sb + 384, m0, n0, lane);

        gemm_tile<false>(zb, sbase + SM_W(4), sbase + SM_W(4), accP, accG, lane, m0, n0);
        epi_g(accP, out + 2L * NROWS * CZ, row0, sb + 512, m0, n0, lane);

        int tn = t + GRID;
        if (tn >= NTILES) break;
        do_ln(x, (long)tn * 128, smem + (buf ? SM_Z0 : SM_Z1), lw4, lb4, wid, lane);
        __syncthreads();
        t = tn;
        buf ^= 1;
    }
}

extern "C" void kernel_launch(void* const* d_in, const int* in_sizes, int n_in,
                              void* d_out, int out_size) {
    const float* x    = (const float*)d_in[0];
    const float* mask = (const float*)d_in[1];
    const float* lnw  = (const float*)d_in[2];
    const float* lnb  = (const float*)d_in[3];
    const float* apw  = (const float*)d_in[4];
    const float* apb  = (const float*)d_in[5];
    const float* agw  = (const float*)d_in[6];
    const float* agb  = (const float*)d_in[7];
    const float* bpw  = (const float*)d_in[8];
    const float* bpb  = (const float*)d_in[9];
    const float* bgw  = (const float*)d_in[10];
    const float* bgb  = (const float*)d_in[11];
    const float* gw   = (const float*)d_in[12];
    const float* gb   = (const float*)d_in[13];
    float* out = (float*)d_out;

    cvt_weights<<<320, 256>>>(apw, agw, bpw, bgw, gw);

    cudaFuncSetAttribute(tri_kernel, cudaFuncAttributeMaxDynamicSharedMemorySize, SMEM_TOTAL);
    tri_kernel<<<GRID, THREADS, SMEM_TOTAL>>>(x, mask, lnw, lnb,
                                              apb, agb, bpb, bgb, gb, out);
}

// round 6
// speedup vs baseline: 1.4406x; 1.0003x over previous
#include <cuda_runtime.h>
#include <cuda_fp16.h>
#include <cstdint>

#define CZ      128
#define NROWS   (512*512)
#define NTILES  2048
#define THREADS 512
#define GRID    152

#define ZROWB   256                 /* bytes per 128-half row */
#define TILE_B  (128*ZROWB)         /* 32768 */

/* smem layout (bytes) */
#define SM_BIAS 0                   /* 640 f32: apb|agb|bpb|bgb|gb (2560 B) */
#define SM_Z0   2560
#define SM_Z1   (SM_Z0 + TILE_B)
#define SM_W(i) (SM_Z1 + TILE_B + (i) * TILE_B)
#define SMEM_TOTAL (SM_W(5))        /* 231936 <= 232448 */

/* fp16 weight scratch, pre-converted + pre-SWIZZLED by prep kernel */
__device__ __align__(16) __half g_wh[5 * 128 * 128];

/* swizzle: 16B chunk index ^= (row & 7). row stride 256B. */
__global__ void cvt_weights(const float* __restrict__ w0, const float* __restrict__ w1,
                            const float* __restrict__ w2, const float* __restrict__ w3,
                            const float* __restrict__ w4) {
    int i = blockIdx.x * blockDim.x + threadIdx.x;   /* 0 .. 81919 */
    int m = i >> 14, idx = i & 16383;
    const float* w = (m == 0) ? w0 : (m == 1) ? w1 : (m == 2) ? w2 : (m == 3) ? w3 : w4;
    int r = idx >> 7, c = idx & 127;
    int pos = r * 128 + ((((c >> 3) ^ (r & 7)) << 3) | (c & 7));
    g_wh[m * 16384 + pos] = __float2half_rn(w[idx]);
}

__device__ __forceinline__ uint32_t smem_u32(const void* p) {
    uint32_t a;
    asm("{ .reg .u64 t; cvta.to.shared.u64 t, %1; cvt.u32.u64 %0, t; }" : "=r"(a) : "l"(p));
    return a;
}

__device__ __forceinline__ void cp16(uint32_t s, uint64_t g) {
    asm volatile("cp.async.cg.shared.global [%0], [%1], 16;" :: "r"(s), "l"(g) : "memory");
}
#define CP_COMMIT() asm volatile("cp.async.commit_group;" ::: "memory")
#define CP_WAIT0()  asm volatile("cp.async.wait_group 0;" ::: "memory")
#define BAR_SYNC(id) asm volatile("bar.sync %0, 128;" :: "r"(id) : "memory")

__device__ __forceinline__ void ldm_x4(uint32_t (&d)[4], uint32_t a) {
    asm volatile("ldmatrix.sync.aligned.m8n8.x4.shared.b16 {%0,%1,%2,%3}, [%4];"
                 : "=r"(d[0]), "=r"(d[1]), "=r"(d[2]), "=r"(d[3]) : "r"(a));
}
__device__ __forceinline__ void mma16816(float (&c)[4], const uint32_t (&a)[4],
                                         uint32_t b0, uint32_t b1) {
    asm volatile("mma.sync.aligned.m16n8k16.row.col.f32.f16.f16.f32 "
                 "{%0,%1,%2,%3}, {%4,%5,%6,%7}, {%8,%9}, {%0,%1,%2,%3};"
                 : "+f"(c[0]), "+f"(c[1]), "+f"(c[2]), "+f"(c[3])
                 : "r"(a[0]), "r"(a[1]), "r"(a[2]), "r"(a[3]), "r"(b0), "r"(b1));
}

/* fused gemm, warp tile m32 x n32; PAIR: two weight matrices share the A fragments.
   One-deep prefetch of the a0 fragment to cover the per-kt LDS bubble. */
template <bool PAIR>
__device__ __forceinline__ void gemm_tile(uint32_t zb, uint32_t wp, uint32_t wg,
                                          float (&accP)[2][4][4], float (&accG)[2][4][4],
                                          int lane, int m0, int n0) {
#pragma unroll
    for (int mt = 0; mt < 2; mt++)
#pragma unroll
        for (int nt = 0; nt < 4; nt++)
#pragma unroll
            for (int r = 0; r < 4; r++) { accP[mt][nt][r] = 0.f; if (PAIR) accG[mt][nt][r] = 0.f; }

    const uint32_t r  = (uint32_t)(lane & 15);
    const uint32_t s  = (uint32_t)(lane >> 4);
    const uint32_t x7 = (uint32_t)(lane & 7);
    const uint32_t za0 = zb + (uint32_t)(m0 + r) * ZROWB;
    const uint32_t za1 = za0 + 16 * ZROWB;
    const uint32_t wp0 = wp + (uint32_t)(n0 + r) * ZROWB;
    const uint32_t wp1 = wp0 + 16 * ZROWB;
    const uint32_t wg0 = wg + (uint32_t)(n0 + r) * ZROWB;
    const uint32_t wg1 = wg0 + 16 * ZROWB;

    uint32_t a0[4];
    ldm_x4(a0, za0 + ((s ^ x7) << 4));          /* prefetch a0 for kt=0 */

#pragma unroll
    for (int kt = 0; kt < 8; kt++) {
        const uint32_t off = (((uint32_t)(2 * kt) + s) ^ x7) << 4;
        uint32_t a1[4], bp0[4], bp1[4];
        ldm_x4(a1, za1 + off);
        ldm_x4(bp0, wp0 + off);
        ldm_x4(bp1, wp1 + off);
        uint32_t bg0[4], bg1[4];
        if (PAIR) {
            ldm_x4(bg0, wg0 + off);
            ldm_x4(bg1, wg1 + off);
        }
        uint32_t na0[4];
        if (kt < 7) {
            const uint32_t offn = (((uint32_t)(2 * kt + 2) + s) ^ x7) << 4;
            ldm_x4(na0, za0 + offn);            /* prefetch a0 for kt+1 */
        }
        mma16816(accP[0][0], a0, bp0[0], bp0[2]); mma16816(accP[0][1], a0, bp0[1], bp0[3]);
        mma16816(accP[0][2], a0, bp1[0], bp1[2]); mma16816(accP[0][3], a0, bp1[1], bp1[3]);
        mma16816(accP[1][0], a1, bp0[0], bp0[2]); mma16816(accP[1][1], a1, bp0[1], bp0[3]);
        mma16816(accP[1][2], a1, bp1[0], bp1[2]); mma16816(accP[1][3], a1, bp1[1], bp1[3]);
        if (PAIR) {
            mma16816(accG[0][0], a0, bg0[0], bg0[2]); mma16816(accG[0][1], a0, bg0[1], bg0[3]);
            mma16816(accG[0][2], a0, bg1[0], bg1[2]); mma16816(accG[0][3], a0, bg1[1], bg1[3]);
            mma16816(accG[1][0], a1, bg0[0], bg0[2]); mma16816(accG[1][1], a1, bg0[1], bg0[3]);
            mma16816(accG[1][2], a1, bg1[0], bg1[2]); mma16816(accG[1][3], a1, bg1[1], bg1[3]);
        }
        if (kt < 7) {
#pragma unroll
            for (int q = 0; q < 4; q++) a0[q] = na0[q];
        }
    }
}

__device__ __forceinline__ float sigmf(float v) { return 1.0f / (1.0f + __expf(-v)); }

__device__ __forceinline__ void epi_pair(const float (&p)[2][4][4], const float (&g)[2][4][4],
                                         float* __restrict__ ob, long row0,
                                         const float* __restrict__ maskg,
                                         const float* __restrict__ pb,
                                         const float* __restrict__ gbv,
                                         int m0, int n0, int lane) {
    int tig = lane & 3, grp = lane >> 2;
#pragma unroll
    for (int mt = 0; mt < 2; mt++) {
        int ra = m0 + mt * 16 + grp, rb = ra + 8;
        float ma = __ldg(maskg + row0 + ra), mb = __ldg(maskg + row0 + rb);
        float* pa = ob + (row0 + ra) * CZ;
        float* pz = ob + (row0 + rb) * CZ;
#pragma unroll
        for (int nt = 0; nt < 4; nt++) {
            int c = n0 + nt * 8 + tig * 2;
            float b0 = pb[c], b1 = pb[c + 1], g0 = gbv[c], g1 = gbv[c + 1];
            float2 v0, v1;
            v0.x = ma * sigmf(g[mt][nt][0] + g0) * (p[mt][nt][0] + b0);
            v0.y = ma * sigmf(g[mt][nt][1] + g1) * (p[mt][nt][1] + b1);
            v1.x = mb * sigmf(g[mt][nt][2] + g0) * (p[mt][nt][2] + b0);
            v1.y = mb * sigmf(g[mt][nt][3] + g1) * (p[mt][nt][3] + b1);
            *(float2*)(pa + c) = v0;
            *(float2*)(pz + c) = v1;
        }
    }
}

__device__ __forceinline__ void epi_g(const float (&d)[2][4][4], float* __restrict__ ob,
                                      long row0, const float* __restrict__ gbv,
                                      int m0, int n0, int lane) {
    int tig = lane & 3, grp = lane >> 2;
#pragma unroll
    for (int mt = 0; mt < 2; mt++) {
        int ra = m0 + mt * 16 + grp, rb = ra + 8;
        float* pa = ob + (row0 + ra) * CZ;
        float* pz = ob + (row0 + rb) * CZ;
#pragma unroll
        for (int nt = 0; nt < 4; nt++) {
            int c = n0 + nt * 8 + tig * 2;
            float g0 = gbv[c], g1 = gbv[c + 1];
            float2 v0, v1;
            v0.x = sigmf(d[mt][nt][0] + g0);
            v0.y = sigmf(d[mt][nt][1] + g1);
            v1.x = sigmf(d[mt][nt][2] + g0);
            v1.y = sigmf(d[mt][nt][3] + g1);
            *(float2*)(pa + c) = v0;
            *(float2*)(pz + c) = v1;
        }
    }
}

/* LayerNorm 8 rows of a 128-row tile into swizzled fp16 z buffer.
   Warp w (m-group g = w>>2, idx = w&3) writes rows g*32 + idx*8 .. +7,
   i.e. exactly the rows its own m-group's gemm will read. */
__device__ __forceinline__ void do_ln(const float* __restrict__ x, long row0, char* zb,
                                      const float4& w4, const float4& b4,
                                      int rbase, int lane) {
    const uint32_t chunk = (uint32_t)(lane >> 1);
    const uint32_t sub   = (uint32_t)(lane & 1) << 3;
#pragma unroll 4
    for (int i = 0; i < 8; i++) {
        int r = rbase + i;
        float4 v = *(const float4*)(x + (row0 + r) * CZ + lane * 4);
        float s  = v.x + v.y + v.z + v.w;
        float ss = v.x * v.x + v.y * v.y + v.z * v.z + v.w * v.w;
#pragma unroll
        for (int o = 16; o; o >>= 1) {
            s  += __shfl_xor_sync(0xFFFFFFFFu, s, o);
            ss += __shfl_xor_sync(0xFFFFFFFFu, ss, o);
        }
        float mu  = s * (1.0f / 128.0f);
        float var = ss * (1.0f / 128.0f) - mu * mu;
        float rs  = rsqrtf(var + 1e-5f);
        __half2 h01 = __floats2half2_rn((v.x - mu) * rs * w4.x + b4.x,
                                        (v.y - mu) * rs * w4.y + b4.y);
        __half2 h23 = __floats2half2_rn((v.z - mu) * rs * w4.z + b4.z,
                                        (v.w - mu) * rs * w4.w + b4.w);
        uint2 u;
        u.x = *(uint32_t*)&h01;
        u.y = *(uint32_t*)&h23;
        uint32_t sw = ((chunk ^ (uint32_t)(r & 7)) << 4) | sub;
        *(uint2*)(zb + (uint32_t)r * ZROWB + sw) = u;
    }
}

__global__ void __launch_bounds__(THREADS, 1)
tri_kernel(const float* __restrict__ x,   const float* __restrict__ mask,
           const float* __restrict__ lnw, const float* __restrict__ lnb,
           const float* __restrict__ apb, const float* __restrict__ agb,
           const float* __restrict__ bpb, const float* __restrict__ bgb,
           const float* __restrict__ gb,  float* __restrict__ out) {
    extern __shared__ char smem[];
    const uint32_t sbase = smem_u32(smem);
    const int tid = threadIdx.x, wid = tid >> 5, lane = tid & 31;
    /* 16 warps: 4 m-groups x 4 n-groups; warp tile m32 x n32 */
    const int mgrp = wid >> 2;
    const int m0 = mgrp * 32, n0 = (wid & 3) * 32;
    const int lnrow = m0 + (wid & 3) * 8;   /* LN rows owned by this warp */

    /* one-time: all 5 weight matrices -> resident smem */
    {
        const char* src = (const char*)g_wh;
#pragma unroll
        for (int i = tid; i < 5 * TILE_B / 16; i += THREADS)
            cp16(sbase + SM_W(0) + i * 16, (uint64_t)__cvta_generic_to_global(src + i * 16));
        CP_COMMIT();
    }

    /* one-time: biases */
    float* sb = (float*)(smem + SM_BIAS);
    for (int i = tid; i < 640; i += THREADS) {
        int j = i & 127, which = i >> 7;
        sb[i] = (which == 0) ? apb[j] : (which == 1) ? agb[j] :
                (which == 2) ? bpb[j] : (which == 3) ? bgb[j] : gb[j];
    }

    const float4 lw4 = *(const float4*)(lnw + lane * 4);
    const float4 lb4 = *(const float4*)(lnb + lane * 4);

    int t = blockIdx.x;
    int buf = 0;
    do_ln(x, (long)t * 128, smem + SM_Z0, lw4, lb4, lnrow, lane);
    CP_WAIT0();
    __syncthreads();

    float accP[2][4][4], accG[2][4][4];
    for (;;) {
        const long row0 = (long)t * 128;
        const uint32_t zb = sbase + (buf ? SM_Z1 : SM_Z0);
        const int tn = t + GRID;

        gemm_tile<true>(zb, sbase + SM_W(0), sbase + SM_W(1), accP, accG, lane, m0, n0);
        epi_pair(accP, accG, out, row0, mask, sb, sb + 128, m0, n0, lane);

        /* LN for next tile early: its LDG latency hides under stages b and g */
        if (tn < NTILES)
            do_ln(x, (long)tn * 128, smem + (buf ? SM_Z0 : SM_Z1), lw4, lb4, lnrow, lane);

        gemm_tile<true>(zb, sbase + SM_W(2), sbase + SM_W(3), accP, accG, lane, m0, n0);
        epi_pair(accP, accG, out + (long)NROWS * CZ, row0, mask,
                 sb + 256, sb + 384, m0, n0, lane);

        gemm_tile<false>(zb, sbase + SM_W(4), sbase + SM_W(4), accP, accG, lane, m0, n0);
        epi_g(accP, out + 2L * NROWS * CZ, row0, sb + 512, m0, n0, lane);

        if (tn >= NTILES) break;
        /* per-m-group barrier: the 4 warps of m-group g are the only writers
           AND the only readers of z rows [g*32, g*32+32) */
        BAR_SYNC(1 + mgrp);
        t = tn;
        buf ^= 1;
    }
}

extern "C" void kernel_launch(void* const* d_in, const int* in_sizes, int n_in,
                              void* d_out, int out_size) {
    const float* x    = (const float*)d_in[0];
    const float* mask = (const float*)d_in[1];
    const float* lnw  = (const float*)d_in[2];
    const float* lnb  = (const float*)d_in[3];
    const float* apw  = (const float*)d_in[4];
    const float* apb  = (const float*)d_in[5];
    const float* agw  = (const float*)d_in[6];
    const float* agb  = (const float*)d_in[7];
    const float* bpw  = (const float*)d_in[8];
    const float* bpb  = (const float*)d_in[9];
    const float* bgw  = (const float*)d_in[10];
    const float* bgb  = (const float*)d_in[11];
    const float* gw   = (const float*)d_in[12];
    const float* gb   = (const float*)d_in[13];
    float* out = (float*)d_out;

    cvt_weights<<<320, 256>>>(apw, agw, bpw, bgw, gw);

    cudaFuncSetAttribute(tri_kernel, cudaFuncAttributeMaxDynamicSharedMemorySize, SMEM_TOTAL);
    tri_kernel<<<GRID, THREADS, SMEM_TOTAL>>>(x, mask, lnw, lnb,
                                              apb, agb, bpb, bgb, gb, out);
}

// round 10
// speedup vs baseline: 1.4470x; 1.0045x over previous
#include <cuda_runtime.h>
#include <cuda_fp16.h>
#include <cstdint>

#define CZ      128
#define NROWS   (512*512)
#define NTILES  2048
#define THREADS 512
#define GRID    152

#define ZROWB   256                 /* bytes per 128-half row */
#define TILE_B  (128*ZROWB)         /* 32768 */

/* smem layout (bytes) */
#define SM_BIAS 0                   /* 640 f32: apb|agb|bpb|bgb|gb (2560 B) */
#define SM_Z0   2560
#define SM_Z1   (SM_Z0 + TILE_B)
#define SM_W(i) (SM_Z1 + TILE_B + (i) * TILE_B)
#define SMEM_TOTAL (SM_W(5))        /* 231936 <= 232448 */

/* fp16 weight scratch, pre-converted + pre-SWIZZLED by prep kernel */
__device__ __align__(16) __half g_wh[5 * 128 * 128];

/* swizzle: 16B chunk index ^= (row & 7). row stride 256B. */
__global__ void cvt_weights(const float* __restrict__ w0, const float* __restrict__ w1,
                            const float* __restrict__ w2, const float* __restrict__ w3,
                            const float* __restrict__ w4) {
    int i = blockIdx.x * blockDim.x + threadIdx.x;   /* 0 .. 81919 */
    int m = i >> 14, idx = i & 16383;
    const float* w = (m == 0) ? w0 : (m == 1) ? w1 : (m == 2) ? w2 : (m == 3) ? w3 : w4;
    int r = idx >> 7, c = idx & 127;
    int pos = r * 128 + ((((c >> 3) ^ (r & 7)) << 3) | (c & 7));
    g_wh[m * 16384 + pos] = __float2half_rn(w[idx]);
}

__device__ __forceinline__ uint32_t smem_u32(const void* p) {
    uint32_t a;
    asm("{ .reg .u64 t; cvta.to.shared.u64 t, %1; cvt.u32.u64 %0, t; }" : "=r"(a) : "l"(p));
    return a;
}

__device__ __forceinline__ void cp16(uint32_t s, uint64_t g) {
    asm volatile("cp.async.cg.shared.global [%0], [%1], 16;" :: "r"(s), "l"(g) : "memory");
}
#define CP_COMMIT() asm volatile("cp.async.commit_group;" ::: "memory")
#define CP_WAIT0()  asm volatile("cp.async.wait_group 0;" ::: "memory")
#define BAR_SYNC(id) asm volatile("bar.sync %0, 128;" :: "r"(id) : "memory")

__device__ __forceinline__ void ldm_x4(uint32_t (&d)[4], uint32_t a) {
    asm volatile("ldmatrix.sync.aligned.m8n8.x4.shared.b16 {%0,%1,%2,%3}, [%4];"
                 : "=r"(d[0]), "=r"(d[1]), "=r"(d[2]), "=r"(d[3]) : "r"(a));
}
__device__ __forceinline__ void mma16816(float (&c)[4], const uint32_t (&a)[4],
                                         uint32_t b0, uint32_t b1) {
    asm volatile("mma.sync.aligned.m16n8k16.row.col.f32.f16.f16.f32 "
                 "{%0,%1,%2,%3}, {%4,%5,%6,%7}, {%8,%9}, {%0,%1,%2,%3};"
                 : "+f"(c[0]), "+f"(c[1]), "+f"(c[2]), "+f"(c[3])
                 : "r"(a[0]), "r"(a[1]), "r"(a[2]), "r"(a[3]), "r"(b0), "r"(b1));
}

/* single m32 x n32 x k128 gemm with full 1-deep fragment pipeline (cur+next) */
__device__ __forceinline__ void gemm_one(uint32_t zb, uint32_t wb,
                                         float (&acc)[2][4][4], int lane, int m0, int n0) {
#pragma unroll
    for (int mt = 0; mt < 2; mt++)
#pragma unroll
        for (int nt = 0; nt < 4; nt++)
#pragma unroll
            for (int r = 0; r < 4; r++) acc[mt][nt][r] = 0.f;

    const uint32_t r  = (uint32_t)(lane & 15);
    const uint32_t s  = (uint32_t)(lane >> 4);
    const uint32_t x7 = (uint32_t)(lane & 7);
    const uint32_t za0 = zb + (uint32_t)(m0 + r) * ZROWB;
    const uint32_t za1 = za0 + 16 * ZROWB;
    const uint32_t wb0 = wb + (uint32_t)(n0 + r) * ZROWB;
    const uint32_t wb1 = wb0 + 16 * ZROWB;

    uint32_t a0[4], a1[4], b0[4], b1[4];
    {
        const uint32_t off = ((s) ^ x7) << 4;
        ldm_x4(a0, za0 + off);
        ldm_x4(a1, za1 + off);
        ldm_x4(b0, wb0 + off);
        ldm_x4(b1, wb1 + off);
    }
#pragma unroll
    for (int kt = 0; kt < 8; kt++) {
        uint32_t na0[4], na1[4], nb0[4], nb1[4];
        if (kt < 7) {
            const uint32_t offn = (((uint32_t)(2 * kt + 2) + s) ^ x7) << 4;
            ldm_x4(na0, za0 + offn);
            ldm_x4(na1, za1 + offn);
            ldm_x4(nb0, wb0 + offn);
            ldm_x4(nb1, wb1 + offn);
        }
        mma16816(acc[0][0], a0, b0[0], b0[2]); mma16816(acc[0][1], a0, b0[1], b0[3]);
        mma16816(acc[0][2], a0, b1[0], b1[2]); mma16816(acc[0][3], a0, b1[1], b1[3]);
        mma16816(acc[1][0], a1, b0[0], b0[2]); mma16816(acc[1][1], a1, b0[1], b0[3]);
        mma16816(acc[1][2], a1, b1[0], b1[2]); mma16816(acc[1][3], a1, b1[1], b1[3]);
        if (kt < 7) {
#pragma unroll
            for (int q = 0; q < 4; q++) {
                a0[q] = na0[q]; a1[q] = na1[q]; b0[q] = nb0[q]; b1[q] = nb1[q];
            }
        }
    }
}

/* cheap sigmoid for gated outputs: 1 MUFU (tanh) instead of 2 (ex2 + rcp) */
__device__ __forceinline__ float sigm_t(float v) {
    float t;
    asm("tanh.approx.f32 %0, %1;" : "=f"(t) : "f"(v * 0.5f));
    return fmaf(0.5f, t, 0.5f);
}
__device__ __forceinline__ float sigmf(float v) { return 1.0f / (1.0f + __expf(-v)); }

/* epilogue, m32 x n32 warp tile: out = mask * sigmoid(G + gb) * (P + pb) */
__device__ __forceinline__ void epi_pair(const float (&p)[2][4][4], const float (&g)[2][4][4],
                                         float* __restrict__ ob, long row0,
                                         const float* __restrict__ maskg,
                                         const float* __restrict__ pb,
                                         const float* __restrict__ gbv,
                                         int m0, int n0, int lane) {
    const int tig = lane & 3, grp = lane >> 2;
    const int r0 = m0 + grp;
    const float mk[4] = { __ldg(maskg + row0 + r0),      __ldg(maskg + row0 + r0 + 8),
                          __ldg(maskg + row0 + r0 + 16), __ldg(maskg + row0 + r0 + 24) };
    float* const rp[4] = { ob + (row0 + r0) * CZ,      ob + (row0 + r0 + 8) * CZ,
                           ob + (row0 + r0 + 16) * CZ, ob + (row0 + r0 + 24) * CZ };
#pragma unroll
    for (int nt = 0; nt < 4; nt++) {
        const int c = n0 + nt * 8 + tig * 2;
        const float b0 = pb[c], b1 = pb[c + 1], g0 = gbv[c], g1 = gbv[c + 1];
#pragma unroll
        for (int mt = 0; mt < 2; mt++) {
            float2 v0, v1;
            v0.x = mk[2*mt]   * sigm_t(g[mt][nt][0] + g0) * (p[mt][nt][0] + b0);
            v0.y = mk[2*mt]   * sigm_t(g[mt][nt][1] + g1) * (p[mt][nt][1] + b1);
            v1.x = mk[2*mt+1] * sigm_t(g[mt][nt][2] + g0) * (p[mt][nt][2] + b0);
            v1.y = mk[2*mt+1] * sigm_t(g[mt][nt][3] + g1) * (p[mt][nt][3] + b1);
            *(float2*)(rp[2*mt]   + c) = v0;
            *(float2*)(rp[2*mt+1] + c) = v1;
        }
    }
}

__device__ __forceinline__ void epi_g(const float (&d)[2][4][4], float* __restrict__ ob,
                                      long row0, const float* __restrict__ gbv,
                                      int m0, int n0, int lane) {
    const int tig = lane & 3, grp = lane >> 2;
    const int r0 = m0 + grp;
    float* const rp[4] = { ob + (row0 + r0) * CZ,      ob + (row0 + r0 + 8) * CZ,
                           ob + (row0 + r0 + 16) * CZ, ob + (row0 + r0 + 24) * CZ };
#pragma unroll
    for (int nt = 0; nt < 4; nt++) {
        const int c = n0 + nt * 8 + tig * 2;
        const float g0 = gbv[c], g1 = gbv[c + 1];
#pragma unroll
        for (int mt = 0; mt < 2; mt++) {
            float2 v0, v1;
            v0.x = sigmf(d[mt][nt][0] + g0);
            v0.y = sigmf(d[mt][nt][1] + g1);
            v1.x = sigmf(d[mt][nt][2] + g0);
            v1.y = sigmf(d[mt][nt][3] + g1);
            *(float2*)(rp[2*mt]   + c) = v0;
            *(float2*)(rp[2*mt+1] + c) = v1;
        }
    }
}

/* LayerNorm 8 rows of a 128-row tile into swizzled fp16 z buffer.
   Warp w (m-group g = w>>2, idx = w&3) writes rows g*32 + idx*8 .. +7. */
__device__ __forceinline__ void do_ln(const float* __restrict__ x, long row0, char* zb,
                                      const float4& w4, const float4& b4,
                                      int rbase, int lane) {
    const uint32_t chunk = (uint32_t)(lane >> 1);
    const uint32_t sub   = (uint32_t)(lane & 1) << 3;
#pragma unroll 4
    for (int i = 0; i < 8; i++) {
        int r = rbase + i;
        float4 v = *(const float4*)(x + (row0 + r) * CZ + lane * 4);
        float s  = v.x + v.y + v.z + v.w;
        float ss = v.x * v.x + v.y * v.y + v.z * v.z + v.w * v.w;
#pragma unroll
        for (int o = 16; o; o >>= 1) {
            s  += __shfl_xor_sync(0xFFFFFFFFu, s, o);
            ss += __shfl_xor_sync(0xFFFFFFFFu, ss, o);
        }
        float mu  = s * (1.0f / 128.0f);
        float var = ss * (1.0f / 128.0f) - mu * mu;
        float rs  = rsqrtf(var + 1e-5f);
        __half2 h01 = __floats2half2_rn((v.x - mu) * rs * w4.x + b4.x,
                                        (v.y - mu) * rs * w4.y + b4.y);
        __half2 h23 = __floats2half2_rn((v.z - mu) * rs * w4.z + b4.z,
                                        (v.w - mu) * rs * w4.w + b4.w);
        uint2 u;
        u.x = *(uint32_t*)&h01;
        u.y = *(uint32_t*)&h23;
        uint32_t sw = ((chunk ^ (uint32_t)(r & 7)) << 4) | sub;
        *(uint2*)(zb + (uint32_t)r * ZROWB + sw) = u;
    }
}

__global__ void __launch_bounds__(THREADS, 1)
tri_kernel(const float* __restrict__ x,   const float* __restrict__ mask,
           const float* __restrict__ lnw, const float* __restrict__ lnb,
           const float* __restrict__ apb, const float* __restrict__ agb,
           const float* __restrict__ bpb, const float* __restrict__ bgb,
           const float* __restrict__ gb,  float* __restrict__ out) {
    extern __shared__ char smem[];
    const uint32_t sbase = smem_u32(smem);
    const int tid = threadIdx.x, wid = tid >> 5, lane = tid & 31;
    /* 16 warps: 4 m-groups x 4 n-groups; warp tile m32 x n32 */
    const int mgrp = wid >> 2;
    const int m0 = mgrp * 32, n0 = (wid & 3) * 32;
    const int lnrow = m0 + (wid & 3) * 8;   /* LN rows owned by this warp */

    /* one-time: all 5 weight matrices -> resident smem */
    {
        const char* src = (const char*)g_wh;
#pragma unroll
        for (int i = tid; i < 5 * TILE_B / 16; i += THREADS)
            cp16(sbase + SM_W(0) + i * 16, (uint64_t)__cvta_generic_to_global(src + i * 16));
        CP_COMMIT();
    }

    /* one-time: biases */
    float* sb = (float*)(smem + SM_BIAS);
    for (int i = tid; i < 640; i += THREADS) {
        int j = i & 127, which = i >> 7;
        sb[i] = (which == 0) ? apb[j] : (which == 1) ? agb[j] :
                (which == 2) ? bpb[j] : (which == 3) ? bgb[j] : gb[j];
    }

    const float4 lw4 = *(const float4*)(lnw + lane * 4);
    const float4 lb4 = *(const float4*)(lnb + lane * 4);

    int t = blockIdx.x;
    int buf = 0;
    do_ln(x, (long)t * 128, smem + SM_Z0, lw4, lb4, lnrow, lane);
    CP_WAIT0();
    __syncthreads();

    float accP[2][4][4], accG[2][4][4];
    for (;;) {
        const long row0 = (long)t * 128;
        const uint32_t zb = sbase + (buf ? SM_Z1 : SM_Z0);
        const int tn = t + GRID;

        /* stage a */
        gemm_one(zb, sbase + SM_W(0), accP, lane, m0, n0);
        gemm_one(zb, sbase + SM_W(1), accG, lane, m0, n0);
        epi_pair(accP, accG, out, row0, mask, sb, sb + 128, m0, n0, lane);

        /* LN for next tile early: its LDG latency hides under stages b and g */
        if (tn < NTILES)
            do_ln(x, (long)tn * 128, smem + (buf ? SM_Z0 : SM_Z1), lw4, lb4, lnrow, lane);

        /* stage b */
        gemm_one(zb, sbase + SM_W(2), accP, lane, m0, n0);
        gemm_one(zb, sbase + SM_W(3), accG, lane, m0, n0);
        epi_pair(accP, accG, out + (long)NROWS * CZ, row0, mask,
                 sb + 256, sb + 384, m0, n0, lane);

        /* stage g */
        gemm_one(zb, sbase + SM_W(4), accP, lane, m0, n0);
        epi_g(accP, out + 2L * NROWS * CZ, row0, sb + 512, m0, n0, lane);

        if (tn >= NTILES) break;
        /* per-m-group barrier: the 4 warps of m-group g are the only writers
           AND readers of z rows [g*32, g*32+32) */
        BAR_SYNC(1 + mgrp);
        t = tn;
        buf ^= 1;
    }
}

extern "C" void kernel_launch(void* const* d_in, const int* in_sizes, int n_in,
                              void* d_out, int out_size) {
    const float* x    = (const float*)d_in[0];
    const float* mask = (const float*)d_in[1];
    const float* lnw  = (const float*)d_in[2];
    const float* lnb  = (const float*)d_in[3];
    const float* apw  = (const float*)d_in[4];
    const float* apb  = (const float*)d_in[5];
    const float* agw  = (const float*)d_in[6];
    const float* agb  = (const float*)d_in[7];
    const float* bpw  = (const float*)d_in[8];
    const float* bpb  = (const float*)d_in[9];
    const float* bgw  = (const float*)d_in[10];
    const float* bgb  = (const float*)d_in[11];
    const float* gw   = (const float*)d_in[12];
    const float* gb   = (const float*)d_in[13];
    float* out = (float*)d_out;

    cvt_weights<<<320, 256>>>(apw, agw, bpw, bgw, gw);

    cudaFuncSetAttribute(tri_kernel, cudaFuncAttributeMaxDynamicSharedMemorySize, SMEM_TOTAL);
    tri_kernel<<<GRID, THREADS, SMEM_TOTAL>>>(x, mask, lnw, lnb,
                                              apb, agb, bpb, bgb, gb, out);
}